// round 5
// baseline (speedup 1.0000x reference)
#include <cuda_runtime.h>
#include <cuda_bf16.h>
#include <cstdint>

// ---------------------------------------------------------------------------
// GCN_d: z1 = tanh(adj @ (z_igae @ w3))
//        z2 = tanh(adj @ (z1 @ w4))
//        z_hat = adj @ (z2 @ w5)
//        z_hat_adj = sigmoid(z_hat @ z_hat^T)
// Output = concat(z_hat [10000*500], z_hat_adj [10000*10000])
// ---------------------------------------------------------------------------

#define N_ROWS 10000
#define D1 20
#define D2 256
#define D3 128
#define N_INPUT 500

// Scratch (device globals: allocation-free rule)
__device__ float g_t1[N_ROWS * D2];      // z_igae @ w3
__device__ float g_z1[N_ROWS * D2];      // tanh(adj @ t1)
__device__ float g_t2[N_ROWS * D3];      // z1 @ w4
__device__ float g_z2[N_ROWS * D3];      // tanh(adj @ t2)
__device__ float g_t3[N_ROWS * N_INPUT]; // z2 @ w5

// ---------------------------------------------------------------------------
// Classic register-tiled SGEMM: C[M,N] = epi(A[M,K] @ op(B))
//   TRANSB=false: B is [K,N] row-major
//   TRANSB=true : B is [N,K] row-major (C = A @ B^T)
// EPI: 0 = none, 1 = tanh, 2 = sigmoid
// BM=BN=128, BK=8, 256 threads, 8x8 per-thread micro-tile.
// ---------------------------------------------------------------------------
#define BM 128
#define BN 128
#define BK 8
#define TM 8
#define TN 8

template <int EPI, bool TRANSB>
__global__ __launch_bounds__(256, 2)
void sgemm_kernel(const float* __restrict__ A, const float* __restrict__ B,
                  float* __restrict__ C, int M, int N, int K) {
    __shared__ float As[BK][BM];
    __shared__ float Bs[BK][BN];

    const int block_row = blockIdx.y * BM;
    const int block_col = blockIdx.x * BN;
    const int tid = threadIdx.x;

    // compute-thread tile coords
    const int tcol = (tid % 16) * TN;
    const int trow = (tid / 16) * TM;

    // A-tile load mapping: 128 rows x 8 k, float4 along k
    const int a_row = tid >> 1;          // 0..127
    const int a_col = (tid & 1) * 4;     // 0 or 4
    // B-tile load mapping (non-trans): 8 k x 128 n, float4 along n
    const int b_row = tid >> 5;          // 0..7
    const int b_col = (tid & 31) * 4;    // 0..124

    float acc[TM][TN];
#pragma unroll
    for (int i = 0; i < TM; i++)
#pragma unroll
        for (int j = 0; j < TN; j++) acc[i][j] = 0.0f;

    for (int k0 = 0; k0 < K; k0 += BK) {
        // ---- load A tile (transposed into smem: As[k][m]) ----
        {
            const int gr = block_row + a_row;
            const int gc = k0 + a_col;
            float4 v = make_float4(0.f, 0.f, 0.f, 0.f);
            if (gr < M) {
                if (gc + 3 < K) {
                    v = *reinterpret_cast<const float4*>(&A[(int64_t)gr * K + gc]);
                } else {
#pragma unroll
                    for (int i = 0; i < 4; i++)
                        if (gc + i < K) ((float*)&v)[i] = A[(int64_t)gr * K + gc + i];
                }
            }
            As[a_col + 0][a_row] = v.x;
            As[a_col + 1][a_row] = v.y;
            As[a_col + 2][a_row] = v.z;
            As[a_col + 3][a_row] = v.w;
        }
        // ---- load B tile ----
        if (!TRANSB) {
            const int gr = k0 + b_row;
            const int gc = block_col + b_col;
            float4 v = make_float4(0.f, 0.f, 0.f, 0.f);
            if (gr < K) {
                if (gc + 3 < N) {
                    v = *reinterpret_cast<const float4*>(&B[(int64_t)gr * N + gc]);
                } else {
#pragma unroll
                    for (int i = 0; i < 4; i++)
                        if (gc + i < N) ((float*)&v)[i] = B[(int64_t)gr * N + gc + i];
                }
            }
            *reinterpret_cast<float4*>(&Bs[b_row][b_col]) = v;
        } else {
            // B is [N,K]; need Bs[k][n] = B[n, k]
            const int n = block_col + a_row;
            const int gk = k0 + a_col;
            float4 v = make_float4(0.f, 0.f, 0.f, 0.f);
            if (n < N) {
                if (gk + 3 < K) {
                    v = *reinterpret_cast<const float4*>(&B[(int64_t)n * K + gk]);
                } else {
#pragma unroll
                    for (int i = 0; i < 4; i++)
                        if (gk + i < K) ((float*)&v)[i] = B[(int64_t)n * K + gk + i];
                }
            }
            Bs[a_col + 0][a_row] = v.x;
            Bs[a_col + 1][a_row] = v.y;
            Bs[a_col + 2][a_row] = v.z;
            Bs[a_col + 3][a_row] = v.w;
        }
        __syncthreads();

        // ---- compute ----
#pragma unroll
        for (int k = 0; k < BK; k++) {
            float ar[TM], br[TN];
#pragma unroll
            for (int i = 0; i < TM; i++) ar[i] = As[k][trow + i];
#pragma unroll
            for (int j = 0; j < TN; j++) br[j] = Bs[k][tcol + j];
#pragma unroll
            for (int i = 0; i < TM; i++)
#pragma unroll
                for (int j = 0; j < TN; j++) acc[i][j] += ar[i] * br[j];
        }
        __syncthreads();
    }

    // ---- epilogue ----
#pragma unroll
    for (int i = 0; i < TM; i++) {
        const int gr = block_row + trow + i;
        if (gr >= M) continue;
        float* crow = &C[(int64_t)gr * N];
#pragma unroll
        for (int j = 0; j < TN; j += 4) {
            const int gc = block_col + tcol + j;
            float4 v;
            v.x = acc[i][j + 0];
            v.y = acc[i][j + 1];
            v.z = acc[i][j + 2];
            v.w = acc[i][j + 3];
            if (EPI == 1) {
                v.x = tanhf(v.x); v.y = tanhf(v.y);
                v.z = tanhf(v.z); v.w = tanhf(v.w);
            } else if (EPI == 2) {
                v.x = __fdividef(1.0f, 1.0f + __expf(-v.x));
                v.y = __fdividef(1.0f, 1.0f + __expf(-v.y));
                v.z = __fdividef(1.0f, 1.0f + __expf(-v.z));
                v.w = __fdividef(1.0f, 1.0f + __expf(-v.w));
            }
            if (gc + 3 < N) {
                *reinterpret_cast<float4*>(&crow[gc]) = v;
            } else {
#pragma unroll
                for (int e = 0; e < 4; e++)
                    if (gc + e < N) crow[gc + e] = ((float*)&v)[e];
            }
        }
    }
}

template <int EPI, bool TRANSB>
static void launch_gemm(const float* A, const float* B, float* C,
                        int M, int N, int K) {
    dim3 grid((N + BN - 1) / BN, (M + BM - 1) / BM);
    sgemm_kernel<EPI, TRANSB><<<grid, 256>>>(A, B, C, M, N, K);
}

extern "C" void kernel_launch(void* const* d_in, const int* in_sizes, int n_in,
                              void* d_out, int out_size) {
    const float* z_igae = (const float*)d_in[0];  // [10000, 20]
    const float* adj    = (const float*)d_in[1];  // [10000, 10000]
    const float* w3     = (const float*)d_in[2];  // [20, 256]
    const float* w4     = (const float*)d_in[3];  // [256, 128]
    const float* w5     = (const float*)d_in[4];  // [128, 500]

    float* z_hat     = (float*)d_out;                              // [10000, 500]
    float* z_hat_adj = (float*)d_out + (int64_t)N_ROWS * N_INPUT;  // [10000, 10000]

    float *t1, *z1, *t2, *z2, *t3;
    cudaGetSymbolAddress((void**)&t1, g_t1);
    cudaGetSymbolAddress((void**)&z1, g_z1);
    cudaGetSymbolAddress((void**)&t2, g_t2);
    cudaGetSymbolAddress((void**)&z2, g_z2);
    cudaGetSymbolAddress((void**)&t3, g_t3);

    // Layer 1: z1 = tanh(adj @ (z_igae @ w3))
    launch_gemm<0, false>(z_igae, w3, t1, N_ROWS, D2, D1);
    launch_gemm<1, false>(adj, t1, z1, N_ROWS, D2, N_ROWS);

    // Layer 2: z2 = tanh(adj @ (z1 @ w4))
    launch_gemm<0, false>(z1, w4, t2, N_ROWS, D3, D2);
    launch_gemm<1, false>(adj, t2, z2, N_ROWS, D3, N_ROWS);

    // Layer 3 (no activation): z_hat = adj @ (z2 @ w5)
    launch_gemm<0, false>(z2, w5, t3, N_ROWS, N_INPUT, D3);
    launch_gemm<0, false>(adj, t3, z_hat, N_ROWS, N_INPUT, N_ROWS);

    // Reconstruction: z_hat_adj = sigmoid(z_hat @ z_hat^T)
    launch_gemm<2, true>(z_hat, z_hat, z_hat_adj, N_ROWS, N_ROWS, N_INPUT);
}

// round 6
// speedup vs baseline: 3.8191x; 3.8191x over previous
#include <cuda_runtime.h>
#include <cuda_bf16.h>
#include <cstdint>

// ---------------------------------------------------------------------------
// GCN_d: z1 = tanh(adj @ (z_igae @ w3))
//        z2 = tanh(adj @ (z1 @ w4))
//        z_hat = adj @ (z2 @ w5)
//        z_hat_adj = sigmoid(z_hat @ z_hat^T)
// Output = concat(z_hat [10000*500], z_hat_adj [10000*10000])
//
// Strategy: big GEMMs (K=10000 adj-propagations + the 10000x10000 syrk) run
// on tensor cores via mma.sync tf32 with pre-rounded (cvt.rna.tf32) operands.
// Small projection GEMMs stay exact fp32 (register-tiled FFMA).
// ---------------------------------------------------------------------------

#define N_ROWS 10000
#define D1 20
#define D2 256
#define D3 128
#define N_INPUT 500
#define ZR_LD 512   // padded K for the syrk (cols 500..511 stay zero)

// Scratch (device globals: allocation-free rule). Zero-initialized at load.
__device__ float g_adjr[(size_t)N_ROWS * N_ROWS]; // tf32-rounded adj (400MB)
__device__ float g_t1[N_ROWS * D2];               // rna(z_igae @ w3)
__device__ float g_z1[N_ROWS * D2];               // tanh(adj @ t1)
__device__ float g_t2[N_ROWS * D3];               // rna(z1 @ w4)
__device__ float g_z2[N_ROWS * D3];               // tanh(adj @ t2)
__device__ float g_t3[N_ROWS * N_INPUT];          // rna(z2 @ w5)
__device__ float g_zr[N_ROWS * ZR_LD];            // rna(z_hat), K-padded with zeros

// ---------------------------------------------------------------------------
// tf32 helpers
// ---------------------------------------------------------------------------
__device__ __forceinline__ float rna_tf32(float x) {
    uint32_t u;
    asm("cvt.rna.tf32.f32 %0, %1;" : "=r"(u) : "f"(x));
    return __uint_as_float(u);
}

__global__ void round_tf32_kernel(const float4* __restrict__ in,
                                  float4* __restrict__ out, int n4) {
    int i = blockIdx.x * blockDim.x + threadIdx.x;
    int stride = gridDim.x * blockDim.x;
    for (; i < n4; i += stride) {
        float4 v = in[i];
        v.x = rna_tf32(v.x); v.y = rna_tf32(v.y);
        v.z = rna_tf32(v.z); v.w = rna_tf32(v.w);
        out[i] = v;
    }
}

// ---------------------------------------------------------------------------
// Tensor-core tf32 GEMM.
//   C[M,N] = epi( A[M,K] @ B )  with A row-major [M,K] (lda)
//   BT=false: B row-major [K,N] (ldb)
//   BT=true : B row-major [N,K] (ldb)  -> C = A @ B^T
// EPI: 0 none, 1 tanh, 2 sigmoid, 3 none + write rna copy into Caux (ld ZR_LD)
// BM=128, BN=64, BK=32, 256 threads (8 warps as 4x2, 32x32 warp tile),
// 3-stage cp.async pipeline, conflict-free smem layouts.
// ---------------------------------------------------------------------------
#define MBM 128
#define MBN 64
#define MBK 32
#define A_LD 36       // floats; frag bank = (4m+k)%32, all distinct
#define B_LD_KN 72    // Bs[k][n]; bank = (8k+n)%32, distinct
#define B_LD_NK 36    // Bs[n][k]; bank = (4n+k)%32, distinct
#define A_STAGE (MBM * A_LD)     // 4608 floats
#define B_STAGE 2304             // 32*72 == 64*36
#define MMA_SMEM_BYTES ((3 * A_STAGE + 3 * B_STAGE) * 4)  // 82944

__device__ __forceinline__ void cp16(uint32_t dst, const void* src, int sz) {
    asm volatile("cp.async.cg.shared.global [%0], [%1], 16, %2;\n"
                 :: "r"(dst), "l"(src), "r"(sz));
}
__device__ __forceinline__ void cp_commit() {
    asm volatile("cp.async.commit_group;\n" ::: "memory");
}
__device__ __forceinline__ void cp_wait1() {
    asm volatile("cp.async.wait_group 1;\n" ::: "memory");
}

__device__ __forceinline__ void mma_tf32(float* d, const uint32_t* a,
                                         const uint32_t* b) {
    asm volatile(
        "mma.sync.aligned.m16n8k8.row.col.f32.tf32.tf32.f32 "
        "{%0,%1,%2,%3}, {%4,%5,%6,%7}, {%8,%9}, {%0,%1,%2,%3};\n"
        : "+f"(d[0]), "+f"(d[1]), "+f"(d[2]), "+f"(d[3])
        : "r"(a[0]), "r"(a[1]), "r"(a[2]), "r"(a[3]), "r"(b[0]), "r"(b[1]));
}

template <bool BT>
__device__ __forceinline__ void mma_load_tile(
    const float* __restrict__ A, const float* __restrict__ B,
    int lda, int ldb, int M, int N, int K,
    int m0, int n0, int k0, uint32_t sA, uint32_t sB, int tid) {
    // A tile: 128 rows x 32 k -> 1024 x 16B chunks, 4 per thread
#pragma unroll
    for (int j = 0; j < 4; j++) {
        int c = tid + j * 256;
        int row = c >> 3, k4 = (c & 7) << 2;
        int gm = m0 + row, gk = k0 + k4;
        bool ok = (gm < M) && (gk + 4 <= K);
        const float* src = ok ? (A + (size_t)gm * lda + gk) : A;
        cp16(sA + (uint32_t)(row * A_LD + k4) * 4, src, ok ? 16 : 0);
    }
    // B tile: 512 x 16B chunks, 2 per thread
#pragma unroll
    for (int j = 0; j < 2; j++) {
        int c = tid + j * 256;
        if (!BT) {
            int kr = c >> 4, n4 = (c & 15) << 2;
            int gk = k0 + kr, gn = n0 + n4;
            bool ok = (gk < K) && (gn + 4 <= N);
            const float* src = ok ? (B + (size_t)gk * ldb + gn) : B;
            cp16(sB + (uint32_t)(kr * B_LD_KN + n4) * 4, src, ok ? 16 : 0);
        } else {
            int nr = c >> 3, k4 = (c & 7) << 2;
            int gn = n0 + nr, gk = k0 + k4;
            bool ok = (gn < N) && (gk + 4 <= K);
            const float* src = ok ? (B + (size_t)gn * ldb + gk) : B;
            cp16(sB + (uint32_t)(nr * B_LD_NK + k4) * 4, src, ok ? 16 : 0);
        }
    }
}

template <int EPI>
__device__ __forceinline__ void epi_store(float* __restrict__ C,
                                          float* __restrict__ Caux,
                                          int gm, int gn, int M, int N,
                                          int ldc, float v0, float v1) {
    if (gm < M && gn + 1 < N) {
        if (EPI == 1) { v0 = tanhf(v0); v1 = tanhf(v1); }
        if (EPI == 2) {
            v0 = __fdividef(1.0f, 1.0f + __expf(-v0));
            v1 = __fdividef(1.0f, 1.0f + __expf(-v1));
        }
        float2 o; o.x = v0; o.y = v1;
        *reinterpret_cast<float2*>(C + (size_t)gm * ldc + gn) = o;
        if (EPI == 3) {
            float2 r; r.x = rna_tf32(v0); r.y = rna_tf32(v1);
            *reinterpret_cast<float2*>(Caux + (size_t)gm * ZR_LD + gn) = r;
        }
    }
}

template <int EPI, bool BT>
__global__ void __launch_bounds__(256, 2)
mma_gemm(const float* __restrict__ A, const float* __restrict__ B,
         float* __restrict__ C, float* __restrict__ Caux,
         int M, int N, int K, int lda, int ldb, int ldc) {
    extern __shared__ float smem[];
    const int tid = threadIdx.x;
    const int wid = tid >> 5, lane = tid & 31;
    const int wm = (wid >> 1) * 32;      // warp m offset: 0,32,64,96
    const int wn = (wid & 1) * 32;       // warp n offset: 0,32
    const int lr = lane >> 2, lc = lane & 3;

    const int m0 = blockIdx.y * MBM;
    const int n0 = blockIdx.x * MBN;

    uint32_t sbase = (uint32_t)__cvta_generic_to_shared(smem);
    uint32_t sA[3], sB[3];
#pragma unroll
    for (int s = 0; s < 3; s++) {
        sA[s] = sbase + (uint32_t)(s * A_STAGE) * 4;
        sB[s] = sbase + (uint32_t)(3 * A_STAGE + s * B_STAGE) * 4;
    }

    float acc[2][4][4];
#pragma unroll
    for (int mt = 0; mt < 2; mt++)
#pragma unroll
        for (int nt = 0; nt < 4; nt++)
#pragma unroll
            for (int e = 0; e < 4; e++) acc[mt][nt][e] = 0.0f;

    const int kt = (K + MBK - 1) / MBK;  // >= 16 in all our calls

    mma_load_tile<BT>(A, B, lda, ldb, M, N, K, m0, n0, 0, sA[0], sB[0], tid);
    cp_commit();
    mma_load_tile<BT>(A, B, lda, ldb, M, N, K, m0, n0, MBK, sA[1], sB[1], tid);
    cp_commit();

    int s_cur = 0, s_next2 = 2;
    for (int t = 0; t < kt; t++) {
        cp_wait1();
        __syncthreads();
        if (t + 2 < kt)
            mma_load_tile<BT>(A, B, lda, ldb, M, N, K, m0, n0,
                              (t + 2) * MBK, sA[s_next2], sB[s_next2], tid);
        cp_commit();

        const float* As = smem + s_cur * A_STAGE;
        const float* Bs = smem + 3 * A_STAGE + s_cur * B_STAGE;
#pragma unroll
        for (int ks = 0; ks < 4; ks++) {
            const int kb = ks * 8;
            uint32_t a[2][4];
#pragma unroll
            for (int mt = 0; mt < 2; mt++) {
                const int mb = wm + mt * 16;
                a[mt][0] = __float_as_uint(As[(mb + lr) * A_LD + kb + lc]);
                a[mt][1] = __float_as_uint(As[(mb + lr + 8) * A_LD + kb + lc]);
                a[mt][2] = __float_as_uint(As[(mb + lr) * A_LD + kb + lc + 4]);
                a[mt][3] = __float_as_uint(As[(mb + lr + 8) * A_LD + kb + lc + 4]);
            }
            uint32_t b[4][2];
#pragma unroll
            for (int nt = 0; nt < 4; nt++) {
                const int nb = wn + nt * 8 + lr;
                if (!BT) {
                    b[nt][0] = __float_as_uint(Bs[(kb + lc) * B_LD_KN + nb]);
                    b[nt][1] = __float_as_uint(Bs[(kb + lc + 4) * B_LD_KN + nb]);
                } else {
                    b[nt][0] = __float_as_uint(Bs[nb * B_LD_NK + kb + lc]);
                    b[nt][1] = __float_as_uint(Bs[nb * B_LD_NK + kb + lc + 4]);
                }
            }
#pragma unroll
            for (int mt = 0; mt < 2; mt++)
#pragma unroll
                for (int nt = 0; nt < 4; nt++)
                    mma_tf32(acc[mt][nt], a[mt], b[nt]);
        }

        s_cur = (s_cur + 1) % 3;
        s_next2 = (s_next2 + 1) % 3;
    }

    // epilogue: c0=(r,2c) c1=(r,2c+1) c2=(r+8,2c) c3=(r+8,2c+1)
#pragma unroll
    for (int mt = 0; mt < 2; mt++) {
#pragma unroll
        for (int nt = 0; nt < 4; nt++) {
            const int gm = m0 + wm + mt * 16 + lr;
            const int gn = n0 + wn + nt * 8 + lc * 2;
            epi_store<EPI>(C, Caux, gm, gn, M, N, ldc,
                           acc[mt][nt][0], acc[mt][nt][1]);
            epi_store<EPI>(C, Caux, gm + 8, gn, M, N, ldc,
                           acc[mt][nt][2], acc[mt][nt][3]);
        }
    }
}

// ---------------------------------------------------------------------------
// Small exact-fp32 SGEMM (for the tiny projection GEMMs; K = 20/256/128).
// EPI: 3 = round output to tf32 (rna). Output row-major [M,N].
// ---------------------------------------------------------------------------
#define SBM 128
#define SBN 128
#define SBK 8
#define STM 8
#define STN 8

template <int EPI>
__global__ __launch_bounds__(256, 2)
void sgemm_small(const float* __restrict__ A, const float* __restrict__ B,
                 float* __restrict__ C, int M, int N, int K) {
    __shared__ float As[SBK][SBM];
    __shared__ float Bs[SBK][SBN];

    const int block_row = blockIdx.y * SBM;
    const int block_col = blockIdx.x * SBN;
    const int tid = threadIdx.x;
    const int tcol = (tid % 16) * STN;
    const int trow = (tid / 16) * STM;
    const int a_row = tid >> 1;
    const int a_col = (tid & 1) * 4;
    const int b_row = tid >> 5;
    const int b_col = (tid & 31) * 4;

    float acc[STM][STN];
#pragma unroll
    for (int i = 0; i < STM; i++)
#pragma unroll
        for (int j = 0; j < STN; j++) acc[i][j] = 0.0f;

    for (int k0 = 0; k0 < K; k0 += SBK) {
        {
            const int gr = block_row + a_row;
            const int gc = k0 + a_col;
            float4 v = make_float4(0.f, 0.f, 0.f, 0.f);
            if (gr < M) {
                if (gc + 3 < K) {
                    v = *reinterpret_cast<const float4*>(&A[(size_t)gr * K + gc]);
                } else {
#pragma unroll
                    for (int i = 0; i < 4; i++)
                        if (gc + i < K) ((float*)&v)[i] = A[(size_t)gr * K + gc + i];
                }
            }
            As[a_col + 0][a_row] = v.x;
            As[a_col + 1][a_row] = v.y;
            As[a_col + 2][a_row] = v.z;
            As[a_col + 3][a_row] = v.w;
        }
        {
            const int gr = k0 + b_row;
            const int gc = block_col + b_col;
            float4 v = make_float4(0.f, 0.f, 0.f, 0.f);
            if (gr < K) {
                if (gc + 3 < N) {
                    v = *reinterpret_cast<const float4*>(&B[(size_t)gr * N + gc]);
                } else {
#pragma unroll
                    for (int i = 0; i < 4; i++)
                        if (gc + i < N) ((float*)&v)[i] = B[(size_t)gr * N + gc + i];
                }
            }
            *reinterpret_cast<float4*>(&Bs[b_row][b_col]) = v;
        }
        __syncthreads();

#pragma unroll
        for (int k = 0; k < SBK; k++) {
            float ar[STM], br[STN];
#pragma unroll
            for (int i = 0; i < STM; i++) ar[i] = As[k][trow + i];
#pragma unroll
            for (int j = 0; j < STN; j++) br[j] = Bs[k][tcol + j];
#pragma unroll
            for (int i = 0; i < STM; i++)
#pragma unroll
                for (int j = 0; j < STN; j++) acc[i][j] += ar[i] * br[j];
        }
        __syncthreads();
    }

#pragma unroll
    for (int i = 0; i < STM; i++) {
        const int gr = block_row + trow + i;
        if (gr >= M) continue;
        float* crow = &C[(size_t)gr * N];
#pragma unroll
        for (int j = 0; j < STN; j++) {
            const int gc = block_col + tcol + j;
            if (gc < N) {
                float v = acc[i][j];
                if (EPI == 3) v = rna_tf32(v);
                crow[gc] = v;
            }
        }
    }
}

// ---------------------------------------------------------------------------
// Launch
// ---------------------------------------------------------------------------
static inline dim3 mma_grid(int M, int N) {
    return dim3((N + MBN - 1) / MBN, (M + MBM - 1) / MBM);
}

extern "C" void kernel_launch(void* const* d_in, const int* in_sizes, int n_in,
                              void* d_out, int out_size) {
    const float* z_igae = (const float*)d_in[0];  // [10000, 20]
    const float* adj    = (const float*)d_in[1];  // [10000, 10000]
    const float* w3     = (const float*)d_in[2];  // [20, 256]
    const float* w4     = (const float*)d_in[3];  // [256, 128]
    const float* w5     = (const float*)d_in[4];  // [128, 500]

    float* z_hat     = (float*)d_out;                              // [10000, 500]
    float* z_hat_adj = (float*)d_out + (size_t)N_ROWS * N_INPUT;   // [10000, 10000]

    float *adjr, *t1, *z1, *t2, *z2, *t3, *zr;
    cudaGetSymbolAddress((void**)&adjr, g_adjr);
    cudaGetSymbolAddress((void**)&t1, g_t1);
    cudaGetSymbolAddress((void**)&z1, g_z1);
    cudaGetSymbolAddress((void**)&t2, g_t2);
    cudaGetSymbolAddress((void**)&z2, g_z2);
    cudaGetSymbolAddress((void**)&t3, g_t3);
    cudaGetSymbolAddress((void**)&zr, g_zr);

    cudaFuncSetAttribute(mma_gemm<1, false>,
                         cudaFuncAttributeMaxDynamicSharedMemorySize, MMA_SMEM_BYTES);
    cudaFuncSetAttribute(mma_gemm<3, false>,
                         cudaFuncAttributeMaxDynamicSharedMemorySize, MMA_SMEM_BYTES);
    cudaFuncSetAttribute(mma_gemm<2, true>,
                         cudaFuncAttributeMaxDynamicSharedMemorySize, MMA_SMEM_BYTES);

    // 0) tf32-round adj once per call
    round_tf32_kernel<<<8192, 256>>>((const float4*)adj, (float4*)adjr,
                                     (int)(((size_t)N_ROWS * N_ROWS) / 4));

    // 1) t1 = rna(z_igae @ w3)            [10000, 256]
    sgemm_small<3><<<dim3(2, 79), 256>>>(z_igae, w3, t1, N_ROWS, D2, D1);
    // 2) z1 = tanh(adjr @ t1)             [10000, 256]
    mma_gemm<1, false><<<mma_grid(N_ROWS, D2), 256, MMA_SMEM_BYTES>>>(
        adjr, t1, z1, nullptr, N_ROWS, D2, N_ROWS, N_ROWS, D2, D2);
    // 3) t2 = rna(z1 @ w4)                [10000, 128]
    sgemm_small<3><<<dim3(1, 79), 256>>>(z1, w4, t2, N_ROWS, D3, D2);
    // 4) z2 = tanh(adjr @ t2)             [10000, 128]
    mma_gemm<1, false><<<mma_grid(N_ROWS, D3), 256, MMA_SMEM_BYTES>>>(
        adjr, t2, z2, nullptr, N_ROWS, D3, N_ROWS, N_ROWS, D3, D3);
    // 5) t3 = rna(z2 @ w5)                [10000, 500]
    sgemm_small<3><<<dim3(4, 79), 256>>>(z2, w5, t3, N_ROWS, N_INPUT, D3);
    // 6) z_hat = adjr @ t3 (exact out + rna copy into zr, K-padded w/ zeros)
    mma_gemm<3, false><<<mma_grid(N_ROWS, N_INPUT), 256, MMA_SMEM_BYTES>>>(
        adjr, t3, z_hat, zr, N_ROWS, N_INPUT, N_ROWS, N_ROWS, N_INPUT, N_INPUT);
    // 7) z_hat_adj = sigmoid(zr @ zr^T)   [10000, 10000], K = 512 (padded)
    mma_gemm<2, true><<<mma_grid(N_ROWS, N_ROWS), 256, MMA_SMEM_BYTES>>>(
        zr, zr, z_hat_adj, nullptr, N_ROWS, N_ROWS, ZR_LD, ZR_LD, ZR_LD, N_ROWS);
}